// round 1
// baseline (speedup 1.0000x reference)
#include <cuda_runtime.h>
#include <math.h>

// Problem constants
// x:      [4, 2048, 1024]  -> A [M=8192, K=1024]
// W_qkv:  [3072, 1024]
// W_proj: [1024, 1024]
// out:    [4, 2048, 1024]

#define MDIM 8192
#define KDIM 1024

// Scratch (allocation-free): Q/K/V in [B*H=64][T=2048][Dh=64] layout, Y in [B,T,C]
__device__ float g_Q[8388608];
__device__ float g_K[8388608];
__device__ float g_V[8388608];
__device__ float g_Y[8388608];

// ---------------------------------------------------------------------------
// Kernel 1: QKV GEMM.  qkv[m, n] = sum_k x[m,k] * W_qkv[n,k]
// 128x128x16 tile, 256 threads, 8x8 per-thread (split 4+4 at +64 offset for
// conflict-free LDS.128). Epilogue scatters into Q/K/V [B,H,T,Dh].
// ---------------------------------------------------------------------------
__global__ __launch_bounds__(256) void qkv_gemm_kernel(const float* __restrict__ X,
                                                       const float* __restrict__ W)
{
    __shared__ float As[16][128];
    __shared__ float Bs[16][128];
    const int tid = threadIdx.x;
    const int m0 = blockIdx.y << 7;
    const int n0 = blockIdx.x << 7;
    const int lr = tid >> 2;          // 0..63
    const int lk = (tid & 3) << 2;    // 0,4,8,12
    const int tr = (tid >> 4) << 2;   // 0..60 step 4
    const int tc = (tid & 15) << 2;

    float acc[8][8];
#pragma unroll
    for (int i = 0; i < 8; ++i)
#pragma unroll
        for (int j = 0; j < 8; ++j) acc[i][j] = 0.f;

    const float* Ap = X + (size_t)(m0 + lr) * KDIM + lk;
    const float* Bp = W + (size_t)(n0 + lr) * KDIM + lk;

    for (int k0 = 0; k0 < KDIM; k0 += 16) {
#pragma unroll
        for (int h = 0; h < 2; ++h) {
            float4 av = *(const float4*)(Ap + (size_t)h * 64 * KDIM + k0);
            float4 bv = *(const float4*)(Bp + (size_t)h * 64 * KDIM + k0);
            int r = lr + h * 64;
            As[lk + 0][r] = av.x; As[lk + 1][r] = av.y;
            As[lk + 2][r] = av.z; As[lk + 3][r] = av.w;
            Bs[lk + 0][r] = bv.x; Bs[lk + 1][r] = bv.y;
            Bs[lk + 2][r] = bv.z; Bs[lk + 3][r] = bv.w;
        }
        __syncthreads();
#pragma unroll
        for (int kk = 0; kk < 16; ++kk) {
            float a[8], b[8];
            *(float4*)(a)     = *(const float4*)&As[kk][tr];
            *(float4*)(a + 4) = *(const float4*)&As[kk][tr + 64];
            *(float4*)(b)     = *(const float4*)&Bs[kk][tc];
            *(float4*)(b + 4) = *(const float4*)&Bs[kk][tc + 64];
#pragma unroll
            for (int i = 0; i < 8; ++i)
#pragma unroll
                for (int j = 0; j < 8; ++j)
                    acc[i][j] = fmaf(a[i], b[j], acc[i][j]);
        }
        __syncthreads();
    }

    // Scatter: n -> (which, head, d); m -> (b, t); dst[((b*16+h)*2048+t)*64+d]
#pragma unroll
    for (int i = 0; i < 8; ++i) {
        int m = m0 + tr + (i & 3) + ((i >> 2) << 6);
        int bb = m >> 11;
        int t = m & 2047;
#pragma unroll
        for (int j = 0; j < 8; ++j) {
            int n = n0 + tc + (j & 3) + ((j >> 2) << 6);
            int which = n >> 10;
            int c = n & 1023;
            int h = c >> 6;
            int d = c & 63;
            float* dst = (which == 0) ? g_Q : (which == 1) ? g_K : g_V;
            dst[(size_t)(((bb << 4) | h) * 2048 + t) * 64 + d] = acc[i][j];
        }
    }
}

// ---------------------------------------------------------------------------
// Kernel 2: Flash attention, fp32. One block = one (b,h) x 64 query rows.
// 256 threads as 16x16; each thread owns 4 rows x 4 cols. Online softmax with
// shfl row-reductions (16-lane groups). Bc = 64, 32 KV tiles.
// ---------------------------------------------------------------------------
__global__ __launch_bounds__(256) void flash_kernel()
{
    extern __shared__ float sm[];
    float* Qs = sm;             // [d][r]  64x64
    float* Ks = sm + 4096;      // [d][c]  64x64
    float* Vs = sm + 8192;      // [j][d]  64x64
    float* Ps = sm + 12288;     // [r][j]  64x68 (padded)

    const int tid = threadIdx.x;
    const int tx = tid & 15;
    const int ty = tid >> 4;
    const int bh = blockIdx.y;
    const int q0 = blockIdx.x << 6;

    const float* Qb = g_Q + (size_t)bh * 2048 * 64;
    const float* Kb = g_K + (size_t)bh * 2048 * 64;
    const float* Vb = g_V + (size_t)bh * 2048 * 64;

    // Load Q tile transposed -> Qs[d][r]
#pragma unroll
    for (int it = 0; it < 4; ++it) {
        int idx = tid + (it << 8);
        int r = idx >> 4;
        int d4 = (idx & 15) << 2;
        float4 v = *(const float4*)&Qb[(size_t)(q0 + r) * 64 + d4];
        Qs[(d4 + 0) * 64 + r] = v.x;
        Qs[(d4 + 1) * 64 + r] = v.y;
        Qs[(d4 + 2) * 64 + r] = v.z;
        Qs[(d4 + 3) * 64 + r] = v.w;
    }

    float m_i[4], l_i[4], acc[4][4];
#pragma unroll
    for (int i = 0; i < 4; ++i) {
        m_i[i] = -INFINITY;
        l_i[i] = 0.f;
#pragma unroll
        for (int j = 0; j < 4; ++j) acc[i][j] = 0.f;
    }

    for (int jb = 0; jb < 32; ++jb) {
        __syncthreads();   // protect Ks/Vs/Ps from previous iteration (and Q stores, iter 0)
        int k0 = jb << 6;
#pragma unroll
        for (int it = 0; it < 4; ++it) {
            int idx = tid + (it << 8);
            int c = idx >> 4;
            int d4 = (idx & 15) << 2;
            float4 v = *(const float4*)&Kb[(size_t)(k0 + c) * 64 + d4];
            Ks[(d4 + 0) * 64 + c] = v.x;
            Ks[(d4 + 1) * 64 + c] = v.y;
            Ks[(d4 + 2) * 64 + c] = v.z;
            Ks[(d4 + 3) * 64 + c] = v.w;
            float4 w = *(const float4*)&Vb[(size_t)(k0 + c) * 64 + d4];
            *(float4*)&Vs[c * 64 + d4] = w;
        }
        __syncthreads();

        // S = Q K^T  (4x4 per thread)
        float s[4][4];
#pragma unroll
        for (int i = 0; i < 4; ++i)
#pragma unroll
            for (int j = 0; j < 4; ++j) s[i][j] = 0.f;

#pragma unroll 16
        for (int d = 0; d < 64; ++d) {
            float4 qv = *(const float4*)&Qs[d * 64 + (ty << 2)];
            float4 kv = *(const float4*)&Ks[d * 64 + (tx << 2)];
            float qa[4] = {qv.x, qv.y, qv.z, qv.w};
            float ka[4] = {kv.x, kv.y, kv.z, kv.w};
#pragma unroll
            for (int i = 0; i < 4; ++i)
#pragma unroll
                for (int j = 0; j < 4; ++j)
                    s[i][j] = fmaf(qa[i], ka[j], s[i][j]);
        }

        // scale + online softmax
#pragma unroll
        for (int i = 0; i < 4; ++i) {
#pragma unroll
            for (int j = 0; j < 4; ++j) s[i][j] *= 0.125f;  // 1/sqrt(64)

            float mloc = fmaxf(fmaxf(s[i][0], s[i][1]), fmaxf(s[i][2], s[i][3]));
#pragma unroll
            for (int off = 8; off; off >>= 1)
                mloc = fmaxf(mloc, __shfl_xor_sync(0xffffffffu, mloc, off));

            float mnew = fmaxf(m_i[i], mloc);
            float alpha = __expf(m_i[i] - mnew);
            m_i[i] = mnew;

            float p0 = __expf(s[i][0] - mnew);
            float p1 = __expf(s[i][1] - mnew);
            float p2 = __expf(s[i][2] - mnew);
            float p3 = __expf(s[i][3] - mnew);
            float lloc = (p0 + p1) + (p2 + p3);
#pragma unroll
            for (int off = 8; off; off >>= 1)
                lloc += __shfl_xor_sync(0xffffffffu, lloc, off);
            l_i[i] = l_i[i] * alpha + lloc;

#pragma unroll
            for (int j = 0; j < 4; ++j) acc[i][j] *= alpha;

            float4 pv = make_float4(p0, p1, p2, p3);
            *(float4*)&Ps[((ty << 2) + i) * 68 + (tx << 2)] = pv;
        }
        __syncthreads();

        // O += P @ V
#pragma unroll 4
        for (int j4 = 0; j4 < 64; j4 += 4) {
            float pr[4][4];
#pragma unroll
            for (int i = 0; i < 4; ++i) {
                float4 p4 = *(const float4*)&Ps[((ty << 2) + i) * 68 + j4];
                pr[i][0] = p4.x; pr[i][1] = p4.y; pr[i][2] = p4.z; pr[i][3] = p4.w;
            }
#pragma unroll
            for (int jj = 0; jj < 4; ++jj) {
                float4 vv = *(const float4*)&Vs[(j4 + jj) * 64 + (tx << 2)];
#pragma unroll
                for (int i = 0; i < 4; ++i) {
                    acc[i][0] = fmaf(pr[i][jj], vv.x, acc[i][0]);
                    acc[i][1] = fmaf(pr[i][jj], vv.y, acc[i][1]);
                    acc[i][2] = fmaf(pr[i][jj], vv.z, acc[i][2]);
                    acc[i][3] = fmaf(pr[i][jj], vv.w, acc[i][3]);
                }
            }
        }
    }

    // Normalize and write Y in [B,T,C] layout
    int bb = bh >> 4;
    int h = bh & 15;
#pragma unroll
    for (int i = 0; i < 4; ++i) {
        float inv = 1.f / l_i[i];
        int t = q0 + (ty << 2) + i;
        float4 o = make_float4(acc[i][0] * inv, acc[i][1] * inv,
                               acc[i][2] * inv, acc[i][3] * inv);
        *(float4*)&g_Y[(size_t)(bb * 2048 + t) * 1024 + h * 64 + (tx << 2)] = o;
    }
}

// ---------------------------------------------------------------------------
// Kernel 3: output projection. out[m,n] = sum_k Y[m,k] * W_proj[n,k]
// ---------------------------------------------------------------------------
__global__ __launch_bounds__(256) void proj_gemm_kernel(const float* __restrict__ W,
                                                        float* __restrict__ Out)
{
    __shared__ float As[16][128];
    __shared__ float Bs[16][128];
    const int tid = threadIdx.x;
    const int m0 = blockIdx.y << 7;
    const int n0 = blockIdx.x << 7;
    const int lr = tid >> 2;
    const int lk = (tid & 3) << 2;
    const int tr = (tid >> 4) << 2;
    const int tc = (tid & 15) << 2;

    float acc[8][8];
#pragma unroll
    for (int i = 0; i < 8; ++i)
#pragma unroll
        for (int j = 0; j < 8; ++j) acc[i][j] = 0.f;

    const float* Ap = g_Y + (size_t)(m0 + lr) * KDIM + lk;
    const float* Bp = W + (size_t)(n0 + lr) * KDIM + lk;

    for (int k0 = 0; k0 < KDIM; k0 += 16) {
#pragma unroll
        for (int h = 0; h < 2; ++h) {
            float4 av = *(const float4*)(Ap + (size_t)h * 64 * KDIM + k0);
            float4 bv = *(const float4*)(Bp + (size_t)h * 64 * KDIM + k0);
            int r = lr + h * 64;
            As[lk + 0][r] = av.x; As[lk + 1][r] = av.y;
            As[lk + 2][r] = av.z; As[lk + 3][r] = av.w;
            Bs[lk + 0][r] = bv.x; Bs[lk + 1][r] = bv.y;
            Bs[lk + 2][r] = bv.z; Bs[lk + 3][r] = bv.w;
        }
        __syncthreads();
#pragma unroll
        for (int kk = 0; kk < 16; ++kk) {
            float a[8], b[8];
            *(float4*)(a)     = *(const float4*)&As[kk][tr];
            *(float4*)(a + 4) = *(const float4*)&As[kk][tr + 64];
            *(float4*)(b)     = *(const float4*)&Bs[kk][tc];
            *(float4*)(b + 4) = *(const float4*)&Bs[kk][tc + 64];
#pragma unroll
            for (int i = 0; i < 8; ++i)
#pragma unroll
                for (int j = 0; j < 8; ++j)
                    acc[i][j] = fmaf(a[i], b[j], acc[i][j]);
        }
        __syncthreads();
    }

#pragma unroll
    for (int i = 0; i < 8; ++i) {
        int m = m0 + tr + (i & 3) + ((i >> 2) << 6);
        float4 v0 = make_float4(acc[i][0], acc[i][1], acc[i][2], acc[i][3]);
        float4 v1 = make_float4(acc[i][4], acc[i][5], acc[i][6], acc[i][7]);
        *(float4*)&Out[(size_t)m * 1024 + n0 + tc] = v0;
        *(float4*)&Out[(size_t)m * 1024 + n0 + tc + 64] = v1;
    }
}

// ---------------------------------------------------------------------------
extern "C" void kernel_launch(void* const* d_in, const int* in_sizes, int n_in,
                              void* d_out, int out_size)
{
    (void)in_sizes; (void)n_in; (void)out_size;
    const float* x  = (const float*)d_in[0];
    const float* wq = (const float*)d_in[1];
    const float* wp = (const float*)d_in[2];
    float* out = (float*)d_out;

    const int smem = (12288 + 64 * 68) * 4;  // 66560 B dynamic smem for flash
    cudaFuncSetAttribute(flash_kernel, cudaFuncAttributeMaxDynamicSharedMemorySize, smem);

    qkv_gemm_kernel<<<dim3(24, 64), 256>>>(x, wq);
    flash_kernel<<<dim3(32, 64), 256, smem>>>();
    proj_gemm_kernel<<<dim3(8, 64), 256>>>(wp, out);
}